// round 9
// baseline (speedup 1.0000x reference)
#include <cuda_runtime.h>
#include <math.h>

// 21-qubit / 3-layer QNN statevector sim. State in 256-bit "quad" format:
//   d_state[k] = ulonglong4 for pairs (2k, 2k+1):
//     .x = (re(4k),re(4k+1))  .y = (im(4k),im(4k+1))   [pair 2k]
//     .z, .w = same for pair 2k+1
// amp bit a <-> qubit (20-a); amp bit 0 = f32x2 lane; pair bit b = amp bit b+1.
// Each thread holds 8 pairs: reg j = (i<<1)|p0, i = 256-bit op, p0 = pair bit 0.
// passA: Rot amps 0..12 + CNOT targets 0..9 (perm + lane swap folded into store).
// passB: Rot amps 13..20 + CNOT targets 10..19 (perm folded into store).
// 2 rounds per pass, 1 smem trip; shuffle-gates on lane-resident bits.

#define NQ      21
#define NPAIR   (1u << 20)
#define THREADS 512
#define TILEP   4096
#define SMEMB   (TILEP * 16 + 768)
#define NBLK    256

typedef unsigned long long u64;

__device__ __align__(32) ulonglong4 d_state[NPAIR / 2];

struct Gate2 { u64 p, q, mq, r, mr, s, ms; };
__device__ Gate2 d_gates[3][NQ];
struct Gate0 { u64 v[6]; };            // (p,p)(r,-r)(-q,q)(-s,-s)(q,-q)(s,s)
__device__ Gate0 d_gate0[3];

__device__ __forceinline__ u64 fma2(u64 a, u64 b, u64 c) {
    u64 d; asm("fma.rn.f32x2 %0,%1,%2,%3;" : "=l"(d) : "l"(a), "l"(b), "l"(c)); return d;
}
__device__ __forceinline__ u64 mul2(u64 a, u64 b) {
    u64 d; asm("mul.rn.f32x2 %0,%1,%2;" : "=l"(d) : "l"(a), "l"(b)); return d;
}
__device__ __forceinline__ float flo(u64 v) { return __uint_as_float((unsigned)v); }
__device__ __forceinline__ float fhi(u64 v) { return __uint_as_float((unsigned)(v >> 32)); }
__device__ __forceinline__ u64 fpack(float a, float b) {
    return (u64)__float_as_uint(a) | ((u64)__float_as_uint(b) << 32);
}
__device__ __forceinline__ u64 swap64(u64 v) { return (v >> 32) | (v << 32); }

// 256-bit state accessors, L2-pinned (.v4.b64 is the legal 256-bit evict_last form)
__device__ __forceinline__ void ld256(const ulonglong4* p, u64& a, u64& b, u64& c, u64& d) {
    asm("ld.global.L2::evict_last.v4.b64 {%0,%1,%2,%3}, [%4];"
        : "=l"(a), "=l"(b), "=l"(c), "=l"(d) : "l"(p));
}
__device__ __forceinline__ void st256(ulonglong4* p, u64 a, u64 b, u64 c, u64 d) {
    asm volatile("st.global.L2::evict_last.v4.b64 [%0], {%1,%2,%3,%4};"
        :: "l"(p), "l"(a), "l"(b), "l"(c), "l"(d) : "memory");
}

__global__ void prep_gates(const float* __restrict__ param, float* __restrict__ out) {
    int t = threadIdx.x;
    if (t == 0) out[0] = 0.f;
    if (t >= 3 * NQ) return;
    int layer = t / NQ, bit = t % NQ, qubit = 20 - bit;
    const float* pp = param + (layer * NQ + qubit) * 3;
    float phi = pp[0], th = pp[1], om = pp[2];
    float s, c;   sincosf(0.5f * th, &s, &c);
    float sa, ca; sincosf(0.5f * (phi + om), &sa, &ca);
    float sb, cb; sincosf(0.5f * (phi - om), &sb, &cb);
    // u00=(p,q)  u01=(r,s)  u10=(-r,s)  u11=(p,-q)
    float p = ca * c, q = -sa * c, r = -cb * s, sv = -sb * s;
    Gate2 g;
    g.p  = fpack(p, p);    g.q  = fpack(q, q);   g.mq = fpack(-q, -q);
    g.r  = fpack(r, r);    g.mr = fpack(-r, -r);
    g.s  = fpack(sv, sv);  g.ms = fpack(-sv, -sv);
    d_gates[layer][bit] = g;
    if (bit == 0) {
        Gate0 g0;
        g0.v[0] = fpack(p, p);    g0.v[1] = fpack(r, -r);
        g0.v[2] = fpack(-q, q);   g0.v[3] = fpack(-sv, -sv);
        g0.v[4] = fpack(q, -q);   g0.v[5] = fpack(sv, sv);
        d_gate0[layer] = g0;
    }
}

template<int S>
__device__ __forceinline__ void vgate(u64 (&re)[8], u64 (&im)[8], const u64* __restrict__ g) {
    const u64 p = g[0], q = g[1], mq = g[2], r = g[3], mr = g[4], s = g[5], ms = g[6];
#pragma unroll
    for (int j = 0; j < 8; j++) {
        if (j & S) continue;
        const int j1 = j | S;
        u64 xr = re[j], xi = im[j], yr = re[j1], yi = im[j1];
        u64 nr0 = fma2(ms, yi, fma2(r,  yr, fma2(mq, xi, mul2(p,  xr))));
        u64 ni0 = fma2(r,  yi, fma2(s,  yr, fma2(p,  xi, mul2(q,  xr))));
        u64 nr1 = fma2(q,  yi, fma2(p,  yr, fma2(ms, xi, mul2(mr, xr))));
        u64 ni1 = fma2(p,  yi, fma2(mq, yr, fma2(mr, xi, mul2(s,  xr))));
        re[j] = nr0; im[j] = ni0; re[j1] = nr1; im[j1] = ni1;
    }
}

template<int B>
__device__ __forceinline__ void hgate(u64 (&re)[8], u64 (&im)[8], const u64* __restrict__ g) {
    const u64 p = g[0], s = g[5], ms = g[6];
    const bool hi = (threadIdx.x >> B) & 1;
    const u64 A  = hi ? g[1] : g[2];   //  q : -q
    const u64 C  = hi ? g[2] : g[1];   // -q :  q
    const u64 Bc = hi ? g[4] : g[3];   // -r :  r
#pragma unroll
    for (int j = 0; j < 8; j++) {
        u64 wr = __shfl_xor_sync(0xffffffffu, re[j], 1 << B);
        u64 wi = __shfl_xor_sync(0xffffffffu, im[j], 1 << B);
        u64 nr = fma2(ms, wi, fma2(Bc, wr, fma2(A, im[j], mul2(p, re[j]))));
        u64 ni = fma2(Bc, wi, fma2(s,  wr, fma2(p, im[j], mul2(C, re[j]))));
        re[j] = nr; im[j] = ni;
    }
}

// In-lane (amp bit 0) gate via packed f32x2 with mixed-sign coefficient pairs.
__device__ __forceinline__ void sgate2(u64 (&re)[8], u64 (&im)[8], const u64* __restrict__ g) {
    const u64 pp = g[0], rmr = g[1], mqq = g[2], msms = g[3], qmq = g[4], ss = g[5];
#pragma unroll
    for (int j = 0; j < 8; j++) {
        u64 sre = swap64(re[j]), sim = swap64(im[j]);
        u64 nr = fma2(msms, sim, fma2(mqq, im[j], fma2(rmr, sre, mul2(pp,  re[j]))));
        u64 ni = fma2(rmr,  sim, fma2(pp,  im[j], fma2(ss,  sre, mul2(qmq, re[j]))));
        re[j] = nr; im[j] = ni;
    }
}

__device__ __forceinline__ float4 packf4(u64 r, u64 i) {
    return make_float4(flo(r), fhi(r), flo(i), fhi(i));
}
__device__ __forceinline__ void unpackf4(float4 v, u64& r, u64& i) {
    r = fpack(v.x, v.y); i = fpack(v.z, v.w);
}

// shared tile index: pair-bit-0 at the top
__device__ __forceinline__ unsigned smidx(unsigned l) {
    return (l >> 1) | ((l & 1u) << 11);
}
// r2 local layout (both passes): bits 0=p0, 1..3=t0..2, 4,5=t5,t6, 6,7=i, 8,9=t3,t4, 10,11=t7,t8
__device__ __forceinline__ unsigned r2l(unsigned t, unsigned i, unsigned p0) {
    return p0 | ((t & 7u) << 1) | (((t >> 5) & 3u) << 4) | (i << 6)
         | (((t >> 3) & 3u) << 8) | ((t >> 7) << 10);
}

// ============================ pass A ============================
// tile = pair bits 0..11 (amps 0..12); gp = blk<<12.
template<int LAYER, bool FIRST>
__global__ void __launch_bounds__(THREADS, 2)
passA_kernel(const float* __restrict__ feat) {
    extern __shared__ char smraw[];
    float4* sm = reinterpret_cast<float4*>(smraw);
    u64* gsm = reinterpret_cast<u64*>(smraw + TILEP * 16);
    const unsigned t = threadIdx.x;
    const unsigned blk = blockIdx.x;
    u64 re[8], im[8];

    // stage gates: [0..5] = gate0 (amp0); amp a in 1..12 at [6 + (a-1)*7]
    if (t < 6)  gsm[t] = reinterpret_cast<const u64*>(&d_gate0[LAYER])[t];
    if (t < 84) gsm[6 + t] = reinterpret_cast<const u64*>(&d_gates[LAYER][1])[t];

    // r1: l = p0 | (t<<1) | (i<<10); quad index = (blk<<11) + t + (i<<9)
#pragma unroll
    for (int i = 0; i < 4; i++) {
        if (FIRST) {
            const float4 v = reinterpret_cast<const float4*>(feat)[(blk << 10) + ((t + (i << 9)) >> 1)]
                ;  // covers 4 amps = pairs (P,P+1) only when t even — handled below
        }
        // (FIRST path handled separately to keep addressing exact)
        if (!FIRST) {
            ld256(&d_state[(blk << 11) + t + (i << 9)], re[2*i], im[2*i], re[2*i+1], im[2*i+1]);
        }
    }
    if (FIRST) {
#pragma unroll
        for (int i = 0; i < 4; i++) {
            // pairs P = gp + 2t + (i<<10), P+1 -> feat floats [2P .. 2P+3]
            float4 v = reinterpret_cast<const float4*>(feat)[(blk << 10) + ((t + (i << 9)) << 0)
                * 1 + 0 + ( (blk<<10)*0 )];
            // feat float4 index = 2P/4 = P/2 = (gp>>1) + t + (i<<9)
            v = reinterpret_cast<const float4*>(feat)[(blk << 11) + t + (i << 9)];
            re[2*i]   = fpack(v.x, v.y); im[2*i]   = 0ull;
            re[2*i+1] = fpack(v.z, v.w); im[2*i+1] = 0ull;
        }
    }
    __syncthreads();                      // gate table visible

    sgate2(re, im, gsm);                  // amp 0
    vgate<1>(re, im, gsm + 6);            // amp 1  (pair 0 = reg bit 0)
    hgate<0>(re, im, gsm + 13);           // amp 2
    hgate<1>(re, im, gsm + 20);           // amp 3
    hgate<2>(re, im, gsm + 27);           // amp 4
    hgate<3>(re, im, gsm + 34);           // amp 5
    hgate<4>(re, im, gsm + 41);           // amp 6
    vgate<2>(re, im, gsm + 76);           // amp 11 (pair 10 = i bit 0)
    vgate<4>(re, im, gsm + 83);           // amp 12
#pragma unroll
    for (int j = 0; j < 8; j++) {
        unsigned l = (unsigned)(j & 1) | (t << 1) | ((unsigned)(j >> 1) << 10);
        sm[smidx(l)] = packf4(re[j], im[j]);
    }
    __syncthreads();

    // r2: i -> pairs 6,7 (amps 7,8); lane bits t3,t4 -> pairs 8,9 (amps 9,10)
#pragma unroll
    for (int j = 0; j < 8; j++) {
        unsigned l = r2l(t, (unsigned)(j >> 1), (unsigned)(j & 1));
        unpackf4(sm[smidx(l)], re[j], im[j]);
    }
    vgate<2>(re, im, gsm + 48);           // amp 7
    vgate<4>(re, im, gsm + 55);           // amp 8
    hgate<3>(re, im, gsm + 62);           // amp 9
    hgate<4>(re, im, gsm + 69);           // amp 10

    // CNOT perm (targets amps 0..9): scatter h = fE(fO(l)); partner l^1 -> h^1.
    // Even-h pair stores as-is; odd-h pair stores lane-swapped (amp0 target).
#pragma unroll
    for (int i = 0; i < 4; i++) {
        unsigned l0 = r2l(t, (unsigned)i, 0u);
        unsigned u = l0 ^ ((l0 >> 1) & 0x155u);
        unsigned h = u ^ ((u >> 1) & 0xAAu);
        const int e = (h & 1u) ? (2*i+1) : (2*i);   // reg landing on even h
        const int o = (h & 1u) ? (2*i)   : (2*i+1);
        st256(&d_state[(blk << 11) + (h >> 1)],
              re[e], im[e], swap64(re[o]), swap64(im[o]));
    }
}

// ============================ pass B ============================
// locals: bit0 = pair 0 (spectator, in-register); bits 1..11 = pairs 9..19.
// quad index for even l: blk | ((l>>1)<<8).
template<int LAYER, bool LAST>
__global__ void __launch_bounds__(THREADS, 2)
passB_kernel(float* __restrict__ out) {
    extern __shared__ char smraw[];
    float4* sm = reinterpret_cast<float4*>(smraw);
    u64* gsm = reinterpret_cast<u64*>(smraw + TILEP * 16);
    const unsigned t = threadIdx.x;
    const unsigned blk = blockIdx.x;
    u64 re[8], im[8];

    // stage gates: amps 13..20 at [(a-13)*7]
    if (t < 56) gsm[t] = reinterpret_cast<const u64*>(&d_gates[LAYER][13])[t];

    // r1: l = p0 | (t<<1) | (i<<10); quad index = blk | ((t + (i<<9)) << 8)
#pragma unroll
    for (int i = 0; i < 4; i++)
        ld256(&d_state[blk | ((t + (i << 9)) << 8)],
              re[2*i], im[2*i], re[2*i+1], im[2*i+1]);
    __syncthreads();                      // gate table visible

    hgate<3>(re, im, gsm + 0);            // amp 13 (local 4)
    hgate<4>(re, im, gsm + 7);            // amp 14 (local 5)
    vgate<2>(re, im, gsm + 42);           // amp 19 (local 10 = i bit 0)
    vgate<4>(re, im, gsm + 49);           // amp 20
#pragma unroll
    for (int j = 0; j < 8; j++) {
        unsigned l = (unsigned)(j & 1) | (t << 1) | ((unsigned)(j >> 1) << 10);
        sm[smidx(l)] = packf4(re[j], im[j]);
    }
    __syncthreads();

    // r2: i -> locals 6,7 (amps 15,16); t3,t4 -> locals 8,9 (amps 17,18)
#pragma unroll
    for (int j = 0; j < 8; j++) {
        unsigned l = r2l(t, (unsigned)(j >> 1), (unsigned)(j & 1));
        unpackf4(sm[smidx(l)], re[j], im[j]);
    }
    vgate<2>(re, im, gsm + 14);           // amp 15
    vgate<4>(re, im, gsm + 21);           // amp 16
    hgate<3>(re, im, gsm + 28);           // amp 17
    hgate<4>(re, im, gsm + 35);           // amp 18

    if (LAST) {
        // Final perm is a bijection preserving amp bit 0 -> skip; sum lo lanes.
        float acc = 0.f;
#pragma unroll
        for (int j = 0; j < 8; j++) {
            float rr = flo(re[j]), ii = flo(im[j]);
            acc += rr * rr + ii * ii;
        }
#pragma unroll
        for (int o = 16; o > 0; o >>= 1)
            acc += __shfl_xor_sync(0xffffffffu, acc, o);
        __syncthreads();
        float* red = reinterpret_cast<float*>(sm);
        if ((t & 31u) == 0) red[t >> 5] = acc;
        __syncthreads();
        if (t == 0) {
            float v = 0.f;
#pragma unroll
            for (int w = 0; w < THREADS / 32; w++) v += red[w];
            atomicAdd(out, v);
        }
        return;
    }

    // CNOT perm (targets amps 10..19 = locals 1..10); h preserves bit 0 (spectator).
#pragma unroll
    for (int i = 0; i < 4; i++) {
        unsigned l0 = r2l(t, (unsigned)i, 0u);
        unsigned u = l0 ^ ((l0 >> 1) & 0x554u);
        unsigned h = u ^ ((u >> 1) & 0x2AAu);
        st256(&d_state[blk | ((h >> 1) << 8)],
              re[2*i], im[2*i], re[2*i+1], im[2*i+1]);
    }
}

extern "C" void kernel_launch(void* const* d_in, const int* in_sizes, int n_in,
                              void* d_out, int out_size) {
    const float* feat  = (const float*)d_in[0];
    const float* param = (const float*)d_in[1];
    float* out = (float*)d_out;

    cudaFuncSetAttribute(passA_kernel<0, true >, cudaFuncAttributeMaxDynamicSharedMemorySize, SMEMB);
    cudaFuncSetAttribute(passA_kernel<1, false>, cudaFuncAttributeMaxDynamicSharedMemorySize, SMEMB);
    cudaFuncSetAttribute(passA_kernel<2, false>, cudaFuncAttributeMaxDynamicSharedMemorySize, SMEMB);
    cudaFuncSetAttribute(passB_kernel<0, false>, cudaFuncAttributeMaxDynamicSharedMemorySize, SMEMB);
    cudaFuncSetAttribute(passB_kernel<1, false>, cudaFuncAttributeMaxDynamicSharedMemorySize, SMEMB);
    cudaFuncSetAttribute(passB_kernel<2, true >, cudaFuncAttributeMaxDynamicSharedMemorySize, SMEMB);

    prep_gates<<<1, 64>>>(param, out);
    passA_kernel<0, true ><<<NBLK, THREADS, SMEMB>>>(feat);
    passB_kernel<0, false><<<NBLK, THREADS, SMEMB>>>(out);
    passA_kernel<1, false><<<NBLK, THREADS, SMEMB>>>(feat);
    passB_kernel<1, false><<<NBLK, THREADS, SMEMB>>>(out);
    passA_kernel<2, false><<<NBLK, THREADS, SMEMB>>>(feat);
    passB_kernel<2, true ><<<NBLK, THREADS, SMEMB>>>(out);
}

// round 10
// speedup vs baseline: 1.5291x; 1.5291x over previous
#include <cuda_runtime.h>
#include <math.h>

// 21-qubit / 3-layer QNN statevector sim. State in "pair format":
//   d_state[h] = float4(re(2h), re(2h+1), im(2h), im(2h+1)),  h = 20-bit pair idx.
// amp bit k <-> qubit (20-k); amp bit 0 = float4 lane; pair bit k = amp bit k+1.
// passA: Rots amps 0..12 + CNOT targets 0..9 (perm + lane swap at store).
// passB: Rots amps 13..20 + CNOT targets 10..19 (perm at store).
// 2 rounds per pass, 1 smem trip; shuffle-gates on lane-resident pair bits.
// Layer-0 passA computes gate matrices in-kernel (no separate prep launch).

#define NQ      21
#define NPAIR   (1u << 20)
#define THREADS 512
#define TILEP   4096
#define SMEMB   (TILEP * 16 + 768)   // tile + gate table
#define NBLK    256

typedef unsigned long long u64;

__device__ float4 d_state[NPAIR];

struct Gate2 { u64 p, q, mq, r, mr, s, ms; };   // f32x2-duplicated coefficients
__device__ Gate2 d_gates[3][NQ];
struct Gate0 { u64 v[6]; };                     // (p,p)(r,-r)(-q,q)(-s,-s)(q,-q)(s,s)
__device__ Gate0 d_gate0[3];

__device__ __forceinline__ u64 fma2(u64 a, u64 b, u64 c) {
    u64 d; asm("fma.rn.f32x2 %0,%1,%2,%3;" : "=l"(d) : "l"(a), "l"(b), "l"(c)); return d;
}
__device__ __forceinline__ u64 mul2(u64 a, u64 b) {
    u64 d; asm("mul.rn.f32x2 %0,%1,%2;" : "=l"(d) : "l"(a), "l"(b)); return d;
}
__device__ __forceinline__ float flo(u64 v) { return __uint_as_float((unsigned)v); }
__device__ __forceinline__ float fhi(u64 v) { return __uint_as_float((unsigned)(v >> 32)); }
__device__ __forceinline__ u64 fpack(float a, float b) {
    return (u64)__float_as_uint(a) | ((u64)__float_as_uint(b) << 32);
}
__device__ __forceinline__ u64 swap64(u64 v) { return (v >> 32) | (v << 32); }
__device__ __forceinline__ unsigned sw(unsigned l) { return l ^ ((l >> 3) & 7u); }

// Rot coefficients: u00=(p,q) u01=(r,s) u10=(-r,s) u11=(p,-q)
__device__ __forceinline__ void gate_coeffs(const float* __restrict__ pp,
                                            float& p, float& q, float& r, float& sv) {
    float phi = pp[0], th = pp[1], om = pp[2];
    float s, c;   sincosf(0.5f * th, &s, &c);
    float sa, ca; sincosf(0.5f * (phi + om), &sa, &ca);
    float sb, cb; sincosf(0.5f * (phi - om), &sb, &cb);
    p = ca * c; q = -sa * c; r = -cb * s; sv = -sb * s;
}

// Paired-register gate on register-index bit S.
template<int S>
__device__ __forceinline__ void vgate(u64 (&re)[8], u64 (&im)[8], const u64* __restrict__ g) {
    const u64 p = g[0], q = g[1], mq = g[2], r = g[3], mr = g[4], s = g[5], ms = g[6];
#pragma unroll
    for (int j = 0; j < 8; j++) {
        if (j & S) continue;
        const int j1 = j | S;
        u64 xr = re[j], xi = im[j], yr = re[j1], yi = im[j1];
        u64 nr0 = fma2(ms, yi, fma2(r,  yr, fma2(mq, xi, mul2(p,  xr))));
        u64 ni0 = fma2(r,  yi, fma2(s,  yr, fma2(p,  xi, mul2(q,  xr))));
        u64 nr1 = fma2(q,  yi, fma2(p,  yr, fma2(ms, xi, mul2(mr, xr))));
        u64 ni1 = fma2(p,  yi, fma2(mq, yr, fma2(mr, xi, mul2(s,  xr))));
        re[j] = nr0; im[j] = ni0; re[j1] = nr1; im[j1] = ni1;
    }
}

// Warp-shuffle gate on lane bit B of threadIdx.
template<int B>
__device__ __forceinline__ void hgate(u64 (&re)[8], u64 (&im)[8], const u64* __restrict__ g) {
    const u64 p = g[0], s = g[5], ms = g[6];
    const bool hi = (threadIdx.x >> B) & 1;
    const u64 A  = hi ? g[1] : g[2];   //  q : -q
    const u64 C  = hi ? g[2] : g[1];   // -q :  q
    const u64 Bc = hi ? g[4] : g[3];   // -r :  r
#pragma unroll
    for (int j = 0; j < 8; j++) {
        u64 wr = __shfl_xor_sync(0xffffffffu, re[j], 1 << B);
        u64 wi = __shfl_xor_sync(0xffffffffu, im[j], 1 << B);
        u64 nr = fma2(ms, wi, fma2(Bc, wr, fma2(A, im[j], mul2(p, re[j]))));
        u64 ni = fma2(Bc, wi, fma2(s,  wr, fma2(p, im[j], mul2(C, re[j]))));
        re[j] = nr; im[j] = ni;
    }
}

// In-lane (amp bit 0) gate via packed f32x2 with mixed-sign coefficient pairs.
// (validated in R8: identical rel_err to scalar form)
__device__ __forceinline__ void sgate2(u64 (&re)[8], u64 (&im)[8], const u64* __restrict__ g) {
    const u64 pp = g[0], rmr = g[1], mqq = g[2], msms = g[3], qmq = g[4], ss = g[5];
#pragma unroll
    for (int j = 0; j < 8; j++) {
        u64 sre = swap64(re[j]), sim = swap64(im[j]);
        u64 nr = fma2(msms, sim, fma2(mqq, im[j], fma2(rmr, sre, mul2(pp,  re[j]))));
        u64 ni = fma2(rmr,  sim, fma2(pp,  im[j], fma2(ss,  sre, mul2(qmq, re[j]))));
        re[j] = nr; im[j] = ni;
    }
}

__device__ __forceinline__ float4 packf4(u64 r, u64 i) {
    return make_float4(flo(r), fhi(r), flo(i), fhi(i));
}
__device__ __forceinline__ void unpackf4(float4 v, u64& r, u64& i) {
    r = fpack(v.x, v.y); i = fpack(v.z, v.w);
}

// r2 layout (both passes): t0..3->l0..3, t5->l4, j->l5..7, t4->l8, t6..8->l9..11
__device__ __forceinline__ unsigned r2i(unsigned t, unsigned j) {
    return (t & 15u) | (((t >> 5) & 1u) << 4) | (j << 5)
         | (((t >> 4) & 1u) << 8) | ((t >> 6) << 9);
}

// ============================ pass A ============================
// tile = pair bits 0..11 (amps 0..12); gsm: gate0 @0..5, amp a (1..12) @ 6+(a-1)*7.
template<int LAYER, bool FIRST>
__global__ void __launch_bounds__(THREADS, 2)
passA_kernel(const float* __restrict__ feat, const float* __restrict__ param,
             float* __restrict__ out) {
    extern __shared__ char smraw[];
    float4* sm = reinterpret_cast<float4*>(smraw);
    u64* gsm = reinterpret_cast<u64*>(smraw + TILEP * 16);
    const unsigned t  = threadIdx.x;
    const unsigned gp = blockIdx.x << 12;
    u64 re[8], im[8];

    if (FIRST) {
        // compute all 63 gate matrices in-kernel; block 0 publishes globals.
        if (t < 3 * NQ) {
            const int layer = t / NQ, bit = t % NQ, qubit = 20 - bit;
            float p, q, r, sv;
            gate_coeffs(param + (layer * NQ + qubit) * 3, p, q, r, sv);
            Gate2 g;
            g.p  = fpack(p, p);    g.q  = fpack(q, q);   g.mq = fpack(-q, -q);
            g.r  = fpack(r, r);    g.mr = fpack(-r, -r);
            g.s  = fpack(sv, sv);  g.ms = fpack(-sv, -sv);
            if (blockIdx.x == 0) d_gates[layer][bit] = g;
            if (layer == 0 && bit >= 1 && bit <= 12) {
                u64* dst = gsm + 6 + (bit - 1) * 7;
                dst[0] = g.p;  dst[1] = g.q;  dst[2] = g.mq; dst[3] = g.r;
                dst[4] = g.mr; dst[5] = g.s;  dst[6] = g.ms;
            }
            if (bit == 0) {
                Gate0 g0;
                g0.v[0] = fpack(p, p);    g0.v[1] = fpack(r, -r);
                g0.v[2] = fpack(-q, q);   g0.v[3] = fpack(-sv, -sv);
                g0.v[4] = fpack(q, -q);   g0.v[5] = fpack(sv, sv);
                if (blockIdx.x == 0) d_gate0[layer] = g0;
                if (layer == 0) {
#pragma unroll
                    for (int k = 0; k < 6; k++) gsm[k] = g0.v[k];
                }
            }
        }
        if (blockIdx.x == 0 && t == 0) out[0] = 0.f;
    } else {
        // stage gate table from globals
        if (t < 6)  gsm[t] = reinterpret_cast<const u64*>(&d_gate0[LAYER])[t];
        if (t < 84) gsm[6 + t] = reinterpret_cast<const u64*>(&d_gates[LAYER][1])[t];
    }

    // r1 (global): l = t | (j<<9); lanes = pairs 0..4 (amps 1..5), j = pairs 9..11
#pragma unroll
    for (int j = 0; j < 8; j++) {
        unsigned l = t | (j << 9);
        if (FIRST) {
            float2 fv = reinterpret_cast<const float2*>(feat)[gp | l];
            re[j] = fpack(fv.x, fv.y); im[j] = 0ull;
        } else {
            unpackf4(d_state[gp | l], re[j], im[j]);
        }
    }
    __syncthreads();                      // gate table visible

    sgate2(re, im, gsm);                  // amp 0
    hgate<0>(re, im, gsm + 6);            // amp 1
    hgate<1>(re, im, gsm + 13);           // amp 2
    hgate<2>(re, im, gsm + 20);           // amp 3
    hgate<3>(re, im, gsm + 27);           // amp 4
    hgate<4>(re, im, gsm + 34);           // amp 5
    vgate<1>(re, im, gsm + 69);           // amp 10 (pair 9 = j bit 0)
    vgate<2>(re, im, gsm + 76);           // amp 11
    vgate<4>(re, im, gsm + 83);           // amp 12
#pragma unroll
    for (int j = 0; j < 8; j++) sm[sw(t | (j << 9))] = packf4(re[j], im[j]);
    __syncthreads();

    // r2: j = pairs 5,6,7 (amps 6,7,8); lane bit 4 -> pair 8 (amp 9)
#pragma unroll
    for (int j = 0; j < 8; j++) unpackf4(sm[sw(r2i(t, j))], re[j], im[j]);
    vgate<1>(re, im, gsm + 41);           // amp 6
    vgate<2>(re, im, gsm + 48);           // amp 7
    vgate<4>(re, im, gsm + 55);           // amp 8
    hgate<4>(re, im, gsm + 62);           // amp 9

    // CNOT perm (targets amps 0..9) inverse-folded into store + lane swap
#pragma unroll
    for (int j = 0; j < 8; j++) {
        unsigned l = r2i(t, j);
        unsigned u = l ^ ((l >> 1) & 0x155u);
        unsigned h = u ^ ((u >> 1) & 0xAAu);
        float4 v = packf4(re[j], im[j]);
        d_state[gp | h] = (h & 1u) ? make_float4(v.y, v.x, v.w, v.z) : v;
    }
}

// ============================ pass B ============================
// tile local bits: 0 = pair 0 (amp1 spectator); 1..11 = pairs 9..19 (amps 10..20).
__device__ __forceinline__ unsigned gpair(unsigned l, unsigned blk) {
    return (l & 1u) | (blk << 1) | ((l >> 1) << 9);
}

template<int LAYER, bool LAST>
__global__ void __launch_bounds__(THREADS, 2)
passB_kernel(float* __restrict__ out) {
    extern __shared__ char smraw[];
    float4* sm = reinterpret_cast<float4*>(smraw);
    u64* gsm = reinterpret_cast<u64*>(smraw + TILEP * 16);
    const unsigned t = threadIdx.x;
    const unsigned blk = blockIdx.x;
    u64 re[8], im[8];

    // stage gate table: amps 13..20 at [(a-13)*7]
    if (t < 56) gsm[t] = reinterpret_cast<const u64*>(&d_gates[LAYER][13])[t];

    // r1 (global): l = t | (j<<9); lane bit 4 = local 4 = amp 13;
    // j = locals 9,10,11 = amps 18,19,20
#pragma unroll
    for (int j = 0; j < 8; j++)
        unpackf4(d_state[gpair(t | (j << 9), blk)], re[j], im[j]);
    __syncthreads();                      // gate table visible

    hgate<4>(re, im, gsm + 0);            // amp 13
    vgate<1>(re, im, gsm + 35);           // amp 18
    vgate<2>(re, im, gsm + 42);           // amp 19
    vgate<4>(re, im, gsm + 49);           // amp 20
#pragma unroll
    for (int j = 0; j < 8; j++) sm[sw(t | (j << 9))] = packf4(re[j], im[j]);
    __syncthreads();

    // r2: j = locals 5,6,7 = amps 14,15,16; lane bit 4 -> local 8 = amp 17
#pragma unroll
    for (int j = 0; j < 8; j++) unpackf4(sm[sw(r2i(t, j))], re[j], im[j]);
    vgate<1>(re, im, gsm + 7);            // amp 14
    vgate<2>(re, im, gsm + 14);           // amp 15
    vgate<4>(re, im, gsm + 21);           // amp 16
    hgate<4>(re, im, gsm + 28);           // amp 17

    if (LAST) {
        // Final perm is a bijection preserving amp bit 0 -> skip; sum lo lanes.
        float acc = 0.f;
#pragma unroll
        for (int j = 0; j < 8; j++) {
            float rr = flo(re[j]), ii = flo(im[j]);
            acc += rr * rr + ii * ii;
        }
#pragma unroll
        for (int o = 16; o > 0; o >>= 1)
            acc += __shfl_xor_sync(0xffffffffu, acc, o);
        __syncthreads();
        float* red = reinterpret_cast<float*>(sm);
        if ((t & 31u) == 0) red[t >> 5] = acc;
        __syncthreads();
        if (t == 0) {
            float v = 0.f;
#pragma unroll
            for (int w = 0; w < THREADS / 32; w++) v += red[w];
            atomicAdd(out, v);
        }
        return;
    }

    // CNOT perm (targets amps 10..19 = locals 1..10) inverse-folded into store
#pragma unroll
    for (int j = 0; j < 8; j++) {
        unsigned l = r2i(t, j);
        unsigned u = l ^ ((l >> 1) & 0x554u);
        unsigned h = u ^ ((u >> 1) & 0x2AAu);
        d_state[gpair(h, blk)] = packf4(re[j], im[j]);
    }
}

extern "C" void kernel_launch(void* const* d_in, const int* in_sizes, int n_in,
                              void* d_out, int out_size) {
    const float* feat  = (const float*)d_in[0];
    const float* param = (const float*)d_in[1];
    float* out = (float*)d_out;

    cudaFuncSetAttribute(passA_kernel<0, true >, cudaFuncAttributeMaxDynamicSharedMemorySize, SMEMB);
    cudaFuncSetAttribute(passA_kernel<1, false>, cudaFuncAttributeMaxDynamicSharedMemorySize, SMEMB);
    cudaFuncSetAttribute(passA_kernel<2, false>, cudaFuncAttributeMaxDynamicSharedMemorySize, SMEMB);
    cudaFuncSetAttribute(passB_kernel<0, false>, cudaFuncAttributeMaxDynamicSharedMemorySize, SMEMB);
    cudaFuncSetAttribute(passB_kernel<1, false>, cudaFuncAttributeMaxDynamicSharedMemorySize, SMEMB);
    cudaFuncSetAttribute(passB_kernel<2, true >, cudaFuncAttributeMaxDynamicSharedMemorySize, SMEMB);

    passA_kernel<0, true ><<<NBLK, THREADS, SMEMB>>>(feat, param, out);
    passB_kernel<0, false><<<NBLK, THREADS, SMEMB>>>(out);
    passA_kernel<1, false><<<NBLK, THREADS, SMEMB>>>(feat, param, out);
    passB_kernel<1, false><<<NBLK, THREADS, SMEMB>>>(out);
    passA_kernel<2, false><<<NBLK, THREADS, SMEMB>>>(feat, param, out);
    passB_kernel<2, true ><<<NBLK, THREADS, SMEMB>>>(out);
}

// round 11
// speedup vs baseline: 1.6117x; 1.0540x over previous
#include <cuda_runtime.h>
#include <math.h>

// 21-qubit / 3-layer QNN statevector sim, with inter-pass layout staging.
// Amplitude pair format: float4(re(2h),re(2h+1),im(2h),im(2h+1)), h = 20-bit pair idx.
// amp bit k <-> qubit (20-k); amp bit 0 = float4 lane; pair bit b = amp bit b+1.
//
// Storage layouts (a = storage address, h = logical pair index):
//   S_B: a = h0 | h[9..19]<<1 | h[1..8]<<12   (written by passA, read by passB)
//   S_A: a = h0 | h[9..11]<<1 | h[1..8]<<4 | h[12..19]<<12  (written by passB, read by passA)
// Both readers see their 12 tile bits as the LOW 12 address bits -> coalesced loads.
//
// passA: Rots amps 0..12 + CNOT targets 0..9 (perm + lane swap folded into store).
// passB: Rots amps 13..20 + CNOT targets 10..19 (perm folded into store).
// 2 rounds/pass, 1 smem trip; shuffle-gates on lane bits; layer0 A does gate prep.

#define NQ      21
#define NPAIR   (1u << 20)
#define THREADS 512
#define TILEP   4096
#define SMEMB   (TILEP * 16 + 768)
#define NBLK    256

typedef unsigned long long u64;

__device__ float4 d_state[NPAIR];

struct Gate2 { u64 p, q, mq, r, mr, s, ms; };
__device__ Gate2 d_gates[3][NQ];
struct Gate0 { u64 v[6]; };              // (p,p)(r,-r)(-q,q)(-s,-s)(q,-q)(s,s)
__device__ Gate0 d_gate0[3];

__device__ __forceinline__ u64 fma2(u64 a, u64 b, u64 c) {
    u64 d; asm("fma.rn.f32x2 %0,%1,%2,%3;" : "=l"(d) : "l"(a), "l"(b), "l"(c)); return d;
}
__device__ __forceinline__ u64 mul2(u64 a, u64 b) {
    u64 d; asm("mul.rn.f32x2 %0,%1,%2;" : "=l"(d) : "l"(a), "l"(b)); return d;
}
__device__ __forceinline__ float flo(u64 v) { return __uint_as_float((unsigned)v); }
__device__ __forceinline__ float fhi(u64 v) { return __uint_as_float((unsigned)(v >> 32)); }
__device__ __forceinline__ u64 fpack(float a, float b) {
    return (u64)__float_as_uint(a) | ((u64)__float_as_uint(b) << 32);
}
__device__ __forceinline__ u64 swap64(u64 v) { return (v >> 32) | (v << 32); }
__device__ __forceinline__ unsigned sw(unsigned l) { return l ^ ((l >> 3) & 7u); }

__device__ __forceinline__ void gate_coeffs(const float* __restrict__ pp,
                                            float& p, float& q, float& r, float& sv) {
    float phi = pp[0], th = pp[1], om = pp[2];
    float s, c;   sincosf(0.5f * th, &s, &c);
    float sa, ca; sincosf(0.5f * (phi + om), &sa, &ca);
    float sb, cb; sincosf(0.5f * (phi - om), &sb, &cb);
    p = ca * c; q = -sa * c; r = -cb * s; sv = -sb * s;
}

template<int S>
__device__ __forceinline__ void vgate(u64 (&re)[8], u64 (&im)[8], const u64* __restrict__ g) {
    const u64 p = g[0], q = g[1], mq = g[2], r = g[3], mr = g[4], s = g[5], ms = g[6];
#pragma unroll
    for (int j = 0; j < 8; j++) {
        if (j & S) continue;
        const int j1 = j | S;
        u64 xr = re[j], xi = im[j], yr = re[j1], yi = im[j1];
        u64 nr0 = fma2(ms, yi, fma2(r,  yr, fma2(mq, xi, mul2(p,  xr))));
        u64 ni0 = fma2(r,  yi, fma2(s,  yr, fma2(p,  xi, mul2(q,  xr))));
        u64 nr1 = fma2(q,  yi, fma2(p,  yr, fma2(ms, xi, mul2(mr, xr))));
        u64 ni1 = fma2(p,  yi, fma2(mq, yr, fma2(mr, xi, mul2(s,  xr))));
        re[j] = nr0; im[j] = ni0; re[j1] = nr1; im[j1] = ni1;
    }
}

template<int B>
__device__ __forceinline__ void hgate(u64 (&re)[8], u64 (&im)[8], const u64* __restrict__ g) {
    const u64 p = g[0], s = g[5], ms = g[6];
    const bool hi = (threadIdx.x >> B) & 1;
    const u64 A  = hi ? g[1] : g[2];
    const u64 C  = hi ? g[2] : g[1];
    const u64 Bc = hi ? g[4] : g[3];
#pragma unroll
    for (int j = 0; j < 8; j++) {
        u64 wr = __shfl_xor_sync(0xffffffffu, re[j], 1 << B);
        u64 wi = __shfl_xor_sync(0xffffffffu, im[j], 1 << B);
        u64 nr = fma2(ms, wi, fma2(Bc, wr, fma2(A, im[j], mul2(p, re[j]))));
        u64 ni = fma2(Bc, wi, fma2(s,  wr, fma2(p, im[j], mul2(C, re[j]))));
        re[j] = nr; im[j] = ni;
    }
}

__device__ __forceinline__ void sgate2(u64 (&re)[8], u64 (&im)[8], const u64* __restrict__ g) {
    const u64 pp = g[0], rmr = g[1], mqq = g[2], msms = g[3], qmq = g[4], ss = g[5];
#pragma unroll
    for (int j = 0; j < 8; j++) {
        u64 sre = swap64(re[j]), sim = swap64(im[j]);
        u64 nr = fma2(msms, sim, fma2(mqq, im[j], fma2(rmr, sre, mul2(pp,  re[j]))));
        u64 ni = fma2(rmr,  sim, fma2(pp,  im[j], fma2(ss,  sre, mul2(qmq, re[j]))));
        re[j] = nr; im[j] = ni;
    }
}

__device__ __forceinline__ float4 packf4(u64 r, u64 i) {
    return make_float4(flo(r), fhi(r), flo(i), fhi(i));
}
__device__ __forceinline__ void unpackf4(float4 v, u64& r, u64& i) {
    r = fpack(v.x, v.y); i = fpack(v.z, v.w);
}

// r2 layout (both passes): t0..3->l0..3, t5->l4, j->l5..7, t4->l8, t6..8->l9..11
__device__ __forceinline__ unsigned r2i(unsigned t, unsigned j) {
    return (t & 15u) | (((t >> 5) & 1u) << 4) | (j << 5)
         | (((t >> 4) & 1u) << 8) | ((t >> 6) << 9);
}

// ============================ pass A ============================
// FIRST: reads feat (identity), locals = pairs 0..11.
// else : reads S_A, locals: l0=pair0, l1..3=pairs 9..11, l4..11=pairs 1..8.
// Both store S_B with CNOT perm (targets amps 0..9) + lane swap folded in.
template<int LAYER, bool FIRST>
__global__ void __launch_bounds__(THREADS, 2)
passA_kernel(const float* __restrict__ feat, const float* __restrict__ param,
             float* __restrict__ out) {
    extern __shared__ char smraw[];
    float4* sm = reinterpret_cast<float4*>(smraw);
    u64* gsm = reinterpret_cast<u64*>(smraw + TILEP * 16);
    const unsigned t   = threadIdx.x;
    const unsigned blk = blockIdx.x;
    u64 re[8], im[8];

    if (FIRST) {
        if (t < 3 * NQ) {
            const int layer = t / NQ, bit = t % NQ, qubit = 20 - bit;
            float p, q, r, sv;
            gate_coeffs(param + (layer * NQ + qubit) * 3, p, q, r, sv);
            Gate2 g;
            g.p  = fpack(p, p);    g.q  = fpack(q, q);   g.mq = fpack(-q, -q);
            g.r  = fpack(r, r);    g.mr = fpack(-r, -r);
            g.s  = fpack(sv, sv);  g.ms = fpack(-sv, -sv);
            if (blk == 0) d_gates[layer][bit] = g;
            if (layer == 0 && bit >= 1 && bit <= 12) {
                u64* dst = gsm + 6 + (bit - 1) * 7;
                dst[0] = g.p;  dst[1] = g.q;  dst[2] = g.mq; dst[3] = g.r;
                dst[4] = g.mr; dst[5] = g.s;  dst[6] = g.ms;
            }
            if (bit == 0) {
                Gate0 g0;
                g0.v[0] = fpack(p, p);    g0.v[1] = fpack(r, -r);
                g0.v[2] = fpack(-q, q);   g0.v[3] = fpack(-sv, -sv);
                g0.v[4] = fpack(q, -q);   g0.v[5] = fpack(sv, sv);
                if (blk == 0) d_gate0[layer] = g0;
                if (layer == 0) {
#pragma unroll
                    for (int k = 0; k < 6; k++) gsm[k] = g0.v[k];
                }
            }
        }
        if (blk == 0 && t == 0) out[0] = 0.f;
    } else {
        if (t < 6)  gsm[t] = reinterpret_cast<const u64*>(&d_gate0[LAYER])[t];
        if (t < 84) gsm[6 + t] = reinterpret_cast<const u64*>(&d_gates[LAYER][1])[t];
    }

    // r1 load: l = t | (j<<9); FIRST from feat (identity), else from S_A (contiguous)
#pragma unroll
    for (int j = 0; j < 8; j++) {
        unsigned l = t | (j << 9);
        if (FIRST) {
            float2 fv = reinterpret_cast<const float2*>(feat)[(blk << 12) | l];
            re[j] = fpack(fv.x, fv.y); im[j] = 0ull;
        } else {
            unpackf4(d_state[(blk << 12) | l], re[j], im[j]);
        }
    }
    __syncthreads();

    sgate2(re, im, gsm);                        // amp 0
    if (FIRST) {
        hgate<0>(re, im, gsm + 6);              // amp 1  (l0 = pair 0)
        hgate<1>(re, im, gsm + 13);             // amp 2
        hgate<2>(re, im, gsm + 20);             // amp 3
        hgate<3>(re, im, gsm + 27);             // amp 4
        hgate<4>(re, im, gsm + 34);             // amp 5
        vgate<1>(re, im, gsm + 69);             // amp 10 (l9)
        vgate<2>(re, im, gsm + 76);             // amp 11
        vgate<4>(re, im, gsm + 83);             // amp 12
    } else {
        hgate<0>(re, im, gsm + 6);              // amp 1  (l0 = pair 0)
        hgate<1>(re, im, gsm + 69);             // amp 10 (l1 = pair 9)
        hgate<2>(re, im, gsm + 76);             // amp 11
        hgate<3>(re, im, gsm + 83);             // amp 12
        hgate<4>(re, im, gsm + 13);             // amp 2  (l4 = pair 1)
        vgate<1>(re, im, gsm + 48);             // amp 7  (l9 = pair 6)
        vgate<2>(re, im, gsm + 55);             // amp 8
        vgate<4>(re, im, gsm + 62);             // amp 9
    }
#pragma unroll
    for (int j = 0; j < 8; j++) sm[sw(t | (j << 9))] = packf4(re[j], im[j]);
    __syncthreads();

    // r2
#pragma unroll
    for (int j = 0; j < 8; j++) unpackf4(sm[sw(r2i(t, j))], re[j], im[j]);
    if (FIRST) {
        vgate<1>(re, im, gsm + 41);             // amp 6 (l5 = pair 5)
        vgate<2>(re, im, gsm + 48);             // amp 7
        vgate<4>(re, im, gsm + 55);             // amp 8
        hgate<4>(re, im, gsm + 62);             // amp 9 (l8 = pair 8)
    } else {
        vgate<1>(re, im, gsm + 20);             // amp 3 (l5 = pair 2)
        vgate<2>(re, im, gsm + 27);             // amp 4
        vgate<4>(re, im, gsm + 34);             // amp 5
        hgate<4>(re, im, gsm + 41);             // amp 6 (l8 = pair 5)
    }

    // perm (targets amps 0..9) in pair space, then store to S_B
#pragma unroll
    for (int j = 0; j < 8; j++) {
        unsigned l = r2i(t, j);
        unsigned z = FIRST ? l
            : ((l & 1u) | (((l >> 4) & 0xFFu) << 1) | (((l >> 1) & 7u) << 9));
        unsigned u = z ^ ((z >> 1) & 0x155u);
        unsigned zh = u ^ ((u >> 1) & 0xAAu);
        unsigned a = (zh & 1u) | (((zh >> 9) & 7u) << 1) | (blk << 4)
                   | (((zh >> 1) & 0xFFu) << 12);
        float4 v = packf4(re[j], im[j]);
        d_state[a] = (zh & 1u) ? make_float4(v.y, v.x, v.w, v.z) : v;
    }
}

// ============================ pass B ============================
// Reads S_B (contiguous): locals l0 = pair 0 (amp1 spectator), l1..11 = pairs 9..19.
// Stores S_A with CNOT perm (targets amps 10..19 = locals 1..10) folded in.
template<int LAYER, bool LAST>
__global__ void __launch_bounds__(THREADS, 2)
passB_kernel(float* __restrict__ out) {
    extern __shared__ char smraw[];
    float4* sm = reinterpret_cast<float4*>(smraw);
    u64* gsm = reinterpret_cast<u64*>(smraw + TILEP * 16);
    const unsigned t = threadIdx.x;
    const unsigned blk = blockIdx.x;
    u64 re[8], im[8];

    if (t < 56) gsm[t] = reinterpret_cast<const u64*>(&d_gates[LAYER][13])[t];

    // r1 load (contiguous): l = t | (j<<9)
#pragma unroll
    for (int j = 0; j < 8; j++)
        unpackf4(d_state[(blk << 12) | (t | (j << 9))], re[j], im[j]);
    __syncthreads();

    hgate<4>(re, im, gsm + 0);            // amp 13 (l4 = pair 12)
    vgate<1>(re, im, gsm + 35);           // amp 18 (l9 = pair 17)
    vgate<2>(re, im, gsm + 42);           // amp 19
    vgate<4>(re, im, gsm + 49);           // amp 20
#pragma unroll
    for (int j = 0; j < 8; j++) sm[sw(t | (j << 9))] = packf4(re[j], im[j]);
    __syncthreads();

    // r2: j = locals 5,6,7 = amps 14,15,16; lane bit 4 -> local 8 = amp 17
#pragma unroll
    for (int j = 0; j < 8; j++) unpackf4(sm[sw(r2i(t, j))], re[j], im[j]);
    vgate<1>(re, im, gsm + 7);            // amp 14
    vgate<2>(re, im, gsm + 14);           // amp 15
    vgate<4>(re, im, gsm + 21);           // amp 16
    hgate<4>(re, im, gsm + 28);           // amp 17

    if (LAST) {
        float acc = 0.f;
#pragma unroll
        for (int j = 0; j < 8; j++) {
            float rr = flo(re[j]), ii = flo(im[j]);
            acc += rr * rr + ii * ii;
        }
#pragma unroll
        for (int o = 16; o > 0; o >>= 1)
            acc += __shfl_xor_sync(0xffffffffu, acc, o);
        __syncthreads();
        float* red = reinterpret_cast<float*>(sm);
        if ((t & 31u) == 0) red[t >> 5] = acc;
        __syncthreads();
        if (t == 0) {
            float v = 0.f;
#pragma unroll
            for (int w = 0; w < THREADS / 32; w++) v += red[w];
            atomicAdd(out, v);
        }
        return;
    }

    // perm on locals, then store to S_A
#pragma unroll
    for (int j = 0; j < 8; j++) {
        unsigned l = r2i(t, j);
        unsigned u = l ^ ((l >> 1) & 0x554u);
        unsigned zh = u ^ ((u >> 1) & 0x2AAu);
        unsigned a = (zh & 1u) | (((zh >> 1) & 7u) << 1) | (blk << 4)
                   | (((zh >> 4) & 0xFFu) << 12);
        d_state[a] = packf4(re[j], im[j]);
    }
}

extern "C" void kernel_launch(void* const* d_in, const int* in_sizes, int n_in,
                              void* d_out, int out_size) {
    const float* feat  = (const float*)d_in[0];
    const float* param = (const float*)d_in[1];
    float* out = (float*)d_out;

    cudaFuncSetAttribute(passA_kernel<0, true >, cudaFuncAttributeMaxDynamicSharedMemorySize, SMEMB);
    cudaFuncSetAttribute(passA_kernel<1, false>, cudaFuncAttributeMaxDynamicSharedMemorySize, SMEMB);
    cudaFuncSetAttribute(passA_kernel<2, false>, cudaFuncAttributeMaxDynamicSharedMemorySize, SMEMB);
    cudaFuncSetAttribute(passB_kernel<0, false>, cudaFuncAttributeMaxDynamicSharedMemorySize, SMEMB);
    cudaFuncSetAttribute(passB_kernel<1, false>, cudaFuncAttributeMaxDynamicSharedMemorySize, SMEMB);
    cudaFuncSetAttribute(passB_kernel<2, true >, cudaFuncAttributeMaxDynamicSharedMemorySize, SMEMB);

    passA_kernel<0, true ><<<NBLK, THREADS, SMEMB>>>(feat, param, out);
    passB_kernel<0, false><<<NBLK, THREADS, SMEMB>>>(out);
    passA_kernel<1, false><<<NBLK, THREADS, SMEMB>>>(feat, param, out);
    passB_kernel<1, false><<<NBLK, THREADS, SMEMB>>>(out);
    passA_kernel<2, false><<<NBLK, THREADS, SMEMB>>>(feat, param, out);
    passB_kernel<2, true ><<<NBLK, THREADS, SMEMB>>>(out);
}